// round 2
// baseline (speedup 1.0000x reference)
#include <cuda_runtime.h>
#include <math.h>

#define NPTS 16384
#define CD   512
#define DIN  1024
#define DST  16
#define DBCW 64       // DT_RANK(32) + 2*D_STATE(32)
#define MLPD 1024
#define NCH  128      // chunks
#define TCH  128      // steps per chunk (NCH*TCH == NPTS)

// ---------------- scratch (device globals; no allocation allowed) ----------------
__device__ __align__(16) float g_f  [NPTS*CD];
__device__ __align__(16) float g_u  [NPTS*CD];       // ln1 out, later reused for x2
__device__ __align__(16) float g_xz [NPTS*2*DIN];
__device__ __align__(16) float g_xc [NPTS*DIN];
__device__ __align__(16) float g_dbc[NPTS*DBCW];
__device__ __align__(16) float g_dt [NPTS*DIN];
__device__ __align__(16) float g_y  [NPTS*DIN];
__device__ __align__(16) float g_x1 [NPTS*CD];
__device__ __align__(16) float g_h2 [NPTS*CD];
__device__ __align__(16) float g_g  [NPTS*MLPD];
__device__ __align__(16) float g_An [DIN*DST];
__device__ __align__(16) float g_Hc [NCH*DIN*DST];
__device__ __align__(16) float g_sd [NCH*DIN];
__device__ __align__(16) float g_hi [NCH*DIN*DST];

// ---------------- generic fp32 GEMM: C = A @ op(B) (+bias)(+add) ----------------
// BT=true : B is (Nn,K) row-major, compute A@B^T.   BT=false: B is (K,Nn) row-major.
template<bool BT>
__global__ __launch_bounds__(256) void sgemm(
    const float* __restrict__ A, int lda,
    const float* __restrict__ B, int ldb,
    const float* __restrict__ bias,
    const float* __restrict__ add,
    float* __restrict__ Cc, int ldc,
    int M, int Nn, int K)
{
    __shared__ float As[8][128];
    __shared__ float Bs[8][128];
    const int tid = threadIdx.x;
    const int tx = tid & 15, ty = tid >> 4;
    const int m0 = blockIdx.y * 128, n0 = blockIdx.x * 128;

    float acc[8][8];
#pragma unroll
    for (int i = 0; i < 8; i++)
#pragma unroll
        for (int j = 0; j < 8; j++) acc[i][j] = 0.f;

    const int arow = tid >> 1, akk = (tid & 1) * 4;

    for (int k0 = 0; k0 < K; k0 += 8) {
        float4 av = *(const float4*)(A + (size_t)(m0 + arow) * lda + k0 + akk);
        As[akk+0][arow] = av.x; As[akk+1][arow] = av.y;
        As[akk+2][arow] = av.z; As[akk+3][arow] = av.w;
        if (BT) {
            float4 bv = make_float4(0.f, 0.f, 0.f, 0.f);
            if (n0 + arow < Nn)
                bv = *(const float4*)(B + (size_t)(n0 + arow) * ldb + k0 + akk);
            Bs[akk+0][arow] = bv.x; Bs[akk+1][arow] = bv.y;
            Bs[akk+2][arow] = bv.z; Bs[akk+3][arow] = bv.w;
        } else {
            int bk = tid >> 5, bn = (tid & 31) * 4;
            float4 bv = make_float4(0.f, 0.f, 0.f, 0.f);
            if (n0 + bn < Nn)
                bv = *(const float4*)(B + (size_t)(k0 + bk) * ldb + n0 + bn);
            *(float4*)(&Bs[bk][bn]) = bv;
        }
        __syncthreads();
#pragma unroll
        for (int kk = 0; kk < 8; kk++) {
            float a[8], b[8];
            float4 a0 = *(const float4*)(&As[kk][ty * 4]);
            float4 a1 = *(const float4*)(&As[kk][ty * 4 + 64]);
            float4 b0 = *(const float4*)(&Bs[kk][tx * 4]);
            float4 b1 = *(const float4*)(&Bs[kk][tx * 4 + 64]);
            a[0]=a0.x; a[1]=a0.y; a[2]=a0.z; a[3]=a0.w;
            a[4]=a1.x; a[5]=a1.y; a[6]=a1.z; a[7]=a1.w;
            b[0]=b0.x; b[1]=b0.y; b[2]=b0.z; b[3]=b0.w;
            b[4]=b1.x; b[5]=b1.y; b[6]=b1.z; b[7]=b1.w;
#pragma unroll
            for (int i = 0; i < 8; i++)
#pragma unroll
                for (int j = 0; j < 8; j++)
                    acc[i][j] = fmaf(a[i], b[j], acc[i][j]);
        }
        __syncthreads();
    }

#pragma unroll
    for (int ih = 0; ih < 2; ih++)
#pragma unroll
    for (int ii = 0; ii < 4; ii++) {
        int m = m0 + ih * 64 + ty * 4 + ii;
#pragma unroll
        for (int jh = 0; jh < 2; jh++) {
            int n = n0 + jh * 64 + tx * 4;
            if (n < Nn) {
                float4 v;
                v.x = acc[ih*4+ii][jh*4+0];
                v.y = acc[ih*4+ii][jh*4+1];
                v.z = acc[ih*4+ii][jh*4+2];
                v.w = acc[ih*4+ii][jh*4+3];
                if (bias) {
                    float4 bb = *(const float4*)(bias + n);
                    v.x += bb.x; v.y += bb.y; v.z += bb.z; v.w += bb.w;
                }
                if (add) {
                    float4 aa = *(const float4*)(add + (size_t)m * ldc + n);
                    v.x += aa.x; v.y += aa.y; v.z += aa.z; v.w += aa.w;
                }
                *(float4*)(Cc + (size_t)m * ldc + n) = v;
            }
        }
    }
}

// ---------------- LayerNorm (optionally gathered input + copy of raw row) ----------------
__global__ __launch_bounds__(128) void ln_kernel(
    const float* __restrict__ in, const int* __restrict__ gidx,
    const float* __restrict__ w, const float* __restrict__ b,
    float* __restrict__ copy_out, float* __restrict__ out)
{
    int row = blockIdx.x;
    int src = gidx ? gidx[row] : row;
    float4 v = *((const float4*)(in + (size_t)src * CD) + threadIdx.x);
    if (copy_out)
        *((float4*)(copy_out + (size_t)row * CD) + threadIdx.x) = v;
    float s  = v.x + v.y + v.z + v.w;
    float ss = v.x*v.x + v.y*v.y + v.z*v.z + v.w*v.w;
#pragma unroll
    for (int o = 16; o; o >>= 1) {
        s  += __shfl_xor_sync(0xffffffffu, s,  o);
        ss += __shfl_xor_sync(0xffffffffu, ss, o);
    }
    __shared__ float sh[10];
    if ((threadIdx.x & 31) == 0) {
        sh[threadIdx.x >> 5] = s;
        sh[4 + (threadIdx.x >> 5)] = ss;
    }
    __syncthreads();
    if (threadIdx.x == 0) {
        float S  = sh[0] + sh[1] + sh[2] + sh[3];
        float SS = sh[4] + sh[5] + sh[6] + sh[7];
        float mu = S * (1.f / CD);
        float var = SS * (1.f / CD) - mu * mu;
        sh[8] = mu;
        sh[9] = rsqrtf(var + 1e-5f);
    }
    __syncthreads();
    float mu = sh[8], r = sh[9];
    float4 wv = *((const float4*)w + threadIdx.x);
    float4 bv = *((const float4*)b + threadIdx.x);
    float4 o;
    o.x = (v.x - mu) * r * wv.x + bv.x;
    o.y = (v.y - mu) * r * wv.y + bv.y;
    o.z = (v.z - mu) * r * wv.z + bv.z;
    o.w = (v.w - mu) * r * wv.w + bv.w;
    *((float4*)(out + (size_t)row * CD) + threadIdx.x) = o;
}

// ---------------- depthwise causal conv1d (k=4) + SiLU ----------------
__global__ void conv_silu_kernel(const float* __restrict__ cw, const float* __restrict__ cb)
{
    int idx = blockIdx.x * blockDim.x + threadIdx.x;   // NPTS*DIN
    int t = idx >> 10, d = idx & 1023;
    float acc = cb[d];
#pragma unroll
    for (int k = 0; k < 4; k++) {
        int tt = t - 3 + k;
        if (tt >= 0) acc = fmaf(g_xz[(size_t)tt * (2*DIN) + d], cw[d * 4 + k], acc);
    }
    float sg = 1.f / (1.f + __expf(-acc));
    g_xc[idx] = acc * sg;
}

__global__ void softplus_kernel()
{
    int i = blockIdx.x * blockDim.x + threadIdx.x;
    float x = g_dt[i];
    g_dt[i] = (x > 0.f) ? (x + log1pf(__expf(-x))) : log1pf(__expf(x));
}

__global__ void aneg_kernel(const float* __restrict__ alog)
{
    int i = blockIdx.x * blockDim.x + threadIdx.x;
    g_An[i] = -__expf(alog[i]);
}

__global__ void gelu_kernel()
{
    int i = blockIdx.x * blockDim.x + threadIdx.x;
    float x = g_g[i];
    g_g[i] = 0.5f * x * (1.f + erff(x * 0.70710678118654752f));
}

// ---------------- scan phase B: per-chunk local scan (h_init = 0) ----------------
__global__ __launch_bounds__(128) void scan_local_kernel()
{
    int d = blockIdx.x * 128 + threadIdx.x;
    int c = blockIdx.y;
    int t0 = c * TCH;
    __shared__ float Bsh[TCH][DST];
    __shared__ float Csh[TCH][DST];
    for (int i = threadIdx.x; i < TCH * DST; i += 128) {
        int t = i >> 4, s = i & 15;
        Bsh[t][s] = g_dbc[(size_t)(t0 + t) * DBCW + 32 + s];
        Csh[t][s] = g_dbc[(size_t)(t0 + t) * DBCW + 48 + s];
    }
    __syncthreads();
    float Av[DST], h[DST];
#pragma unroll
    for (int s = 0; s < DST; s++) { Av[s] = g_An[d * DST + s]; h[s] = 0.f; }
    float dts = 0.f;
    for (int t = 0; t < TCH; t++) {
        float dtv = g_dt[(size_t)(t0 + t) * DIN + d];
        float xv  = g_xc[(size_t)(t0 + t) * DIN + d];
        float dtx = dtv * xv;
        dts += dtv;
        float y = 0.f;
#pragma unroll
        for (int s = 0; s < DST; s++) {
            float a = __expf(dtv * Av[s]);
            h[s] = fmaf(a, h[s], dtx * Bsh[t][s]);
            y = fmaf(h[s], Csh[t][s], y);
        }
        g_y[(size_t)(t0 + t) * DIN + d] = y;
    }
#pragma unroll
    for (int s = 0; s < DST; s++)
        g_Hc[((size_t)c * DIN + d) * DST + s] = h[s];
    g_sd[(size_t)c * DIN + d] = dts;
}

// ---------------- scan phase C: sequential combine over chunk summaries ----------------
__global__ void scan_combine_kernel()
{
    int idx = blockIdx.x * blockDim.x + threadIdx.x;   // DIN*DST
    int d = idx >> 4;
    float Av = g_An[idx];
    float h = 0.f;
    g_hi[idx] = 0.f;                                   // chunk 0 initial state
    for (int c = 1; c < NCH; c++) {
        h = fmaf(__expf(Av * g_sd[(size_t)(c - 1) * DIN + d]), h,
                 g_Hc[(size_t)(c - 1) * DIN * DST + idx]);
        g_hi[(size_t)c * DIN * DST + idx] = h;
    }
}

// ---------------- scan phase D: h_init correction + fused (y + x*D)*silu(z) gate ----------------
__global__ __launch_bounds__(128) void scan_correct_kernel(const float* __restrict__ Dskip)
{
    int d = blockIdx.x * 128 + threadIdx.x;
    int c = blockIdx.y;
    int t0 = c * TCH;
    __shared__ float Csh[TCH][DST];
    for (int i = threadIdx.x; i < TCH * DST; i += 128) {
        int t = i >> 4, s = i & 15;
        Csh[t][s] = g_dbc[(size_t)(t0 + t) * DBCW + 48 + s];
    }
    __syncthreads();
    float Av[DST], hi[DST];
#pragma unroll
    for (int s = 0; s < DST; s++) {
        Av[s] = g_An[d * DST + s];
        hi[s] = g_hi[(size_t)c * DIN * DST + d * DST + s];
    }
    float Dv = Dskip[d];
    float cum = 0.f;
    for (int t = 0; t < TCH; t++) {
        float dtv = g_dt[(size_t)(t0 + t) * DIN + d];
        cum += dtv;
        float corr = 0.f;
#pragma unroll
        for (int s = 0; s < DST; s++)
            corr = fmaf(__expf(Av[s] * cum) * hi[s], Csh[t][s], corr);
        float ysum = g_y[(size_t)(t0 + t) * DIN + d] + corr;
        float xv = g_xc[(size_t)(t0 + t) * DIN + d];
        float zv = g_xz[(size_t)(t0 + t) * (2*DIN) + DIN + d];
        float sg = zv / (1.f + __expf(-zv));
        g_y[(size_t)(t0 + t) * DIN + d] = (ysum + xv * Dv) * sg;
    }
}

// ---------------- final scatter back to original order ----------------
__global__ __launch_bounds__(128) void scatter_kernel(const int* __restrict__ inv, float* __restrict__ out)
{
    int row = blockIdx.x;
    int src = inv[row];
    *((float4*)(out + (size_t)row * CD) + threadIdx.x) =
        *((const float4*)(g_u + (size_t)src * CD) + threadIdx.x);
}

// ---------------- launch ----------------
extern "C" void kernel_launch(void* const* d_in, const int* in_sizes, int n_in,
                              void* d_out, int out_size)
{
    (void)in_sizes; (void)n_in; (void)out_size;
    const float* feat  = (const float*)d_in[0];
    const int*   order = (const int*)  d_in[1];
    const int*   inv   = (const int*)  d_in[2];
    const float* ln1w  = (const float*)d_in[3];
    const float* ln1b  = (const float*)d_in[4];
    const float* inpw  = (const float*)d_in[5];   // (2048, 512)
    const float* convw = (const float*)d_in[6];   // (1024, 4)
    const float* convb = (const float*)d_in[7];
    const float* xpw   = (const float*)d_in[8];   // (64, 1024)
    const float* dtw   = (const float*)d_in[9];   // (1024, 32)
    const float* dtb   = (const float*)d_in[10];
    const float* alog  = (const float*)d_in[11];  // (1024, 16)
    const float* dskip = (const float*)d_in[12];
    const float* outw  = (const float*)d_in[13];  // (512, 1024)
    const float* ln2w  = (const float*)d_in[14];
    const float* ln2b  = (const float*)d_in[15];
    const float* fw1   = (const float*)d_in[16];  // (512, 1024)
    const float* fb1   = (const float*)d_in[17];
    const float* fw2   = (const float*)d_in[18];  // (1024, 512)
    const float* fb2   = (const float*)d_in[19];
    float* out = (float*)d_out;

    void *pf, *pu, *pxz, *pxc, *pdbc, *pdt, *py, *px1, *ph2, *pg;
    cudaGetSymbolAddress(&pf,  g_f);
    cudaGetSymbolAddress(&pu,  g_u);
    cudaGetSymbolAddress(&pxz, g_xz);
    cudaGetSymbolAddress(&pxc, g_xc);
    cudaGetSymbolAddress(&pdbc,g_dbc);
    cudaGetSymbolAddress(&pdt, g_dt);
    cudaGetSymbolAddress(&py,  g_y);
    cudaGetSymbolAddress(&px1, g_x1);
    cudaGetSymbolAddress(&ph2, g_h2);
    cudaGetSymbolAddress(&pg,  g_g);

    // 1) gather + LN1 (stores raw gathered f and normalized u)
    ln_kernel<<<NPTS, 128>>>(feat, order, ln1w, ln1b, (float*)pf, (float*)pu);

    // 2) xz = u @ in_proj_w^T   (16384 x 2048 x 512)
    sgemm<true><<<dim3(16, 128), 256>>>((const float*)pu, CD, inpw, CD,
                                        nullptr, nullptr, (float*)pxz, 2*DIN,
                                        NPTS, 2*DIN, CD);

    // 3) depthwise causal conv + SiLU -> xc
    conv_silu_kernel<<<(NPTS*DIN)/256, 256>>>(convw, convb);

    // 4) dbc = xc @ x_proj_w^T   (16384 x 64 x 1024)
    sgemm<true><<<dim3(1, 128), 256>>>((const float*)pxc, DIN, xpw, DIN,
                                       nullptr, nullptr, (float*)pdbc, DBCW,
                                       NPTS, DBCW, DIN);

    // 5) dt_raw = dbc[:, :32] @ dt_proj_w^T + b, then softplus
    sgemm<true><<<dim3(8, 128), 256>>>((const float*)pdbc, DBCW, dtw, 32,
                                       dtb, nullptr, (float*)pdt, DIN,
                                       NPTS, DIN, 32);
    softplus_kernel<<<(NPTS*DIN)/256, 256>>>();

    // 6) A = -exp(A_log)
    aneg_kernel<<<(DIN*DST)/256, 256>>>(alog);

    // 7) chunked selective scan: local -> combine -> correct(+gate)
    scan_local_kernel<<<dim3(DIN/128, NCH), 128>>>();
    scan_combine_kernel<<<(DIN*DST)/256, 256>>>();
    scan_correct_kernel<<<dim3(DIN/128, NCH), 128>>>(dskip);

    // 8) x1 = f + y @ out_proj_w^T   (16384 x 512 x 1024, fused residual)
    sgemm<true><<<dim3(4, 128), 256>>>((const float*)py, DIN, outw, DIN,
                                       nullptr, (const float*)pf, (float*)px1, CD,
                                       NPTS, CD, DIN);

    // 9) h2 = LN2(x1)
    ln_kernel<<<NPTS, 128>>>((const float*)px1, nullptr, ln2w, ln2b,
                             nullptr, (float*)ph2);

    // 10) g = h2 @ ffn_w1 + b1, GeLU   (16384 x 1024 x 512)
    sgemm<false><<<dim3(8, 128), 256>>>((const float*)ph2, CD, fw1, MLPD,
                                        fb1, nullptr, (float*)pg, MLPD,
                                        NPTS, MLPD, CD);
    gelu_kernel<<<(NPTS*MLPD)/256, 256>>>();

    // 11) x2 = x1 + g @ ffn_w2 + b2   (16384 x 512 x 1024, fused residual) -> g_u
    sgemm<false><<<dim3(4, 128), 256>>>((const float*)pg, MLPD, fw2, CD,
                                        fb2, (const float*)px1, (float*)pu, CD,
                                        NPTS, CD, MLPD);

    // 12) out[i] = x2[inverse[i]]
    scatter_kernel<<<NPTS, 128>>>(inv, out);
}

// round 4
// speedup vs baseline: 2.2728x; 2.2728x over previous
#include <cuda_runtime.h>
#include <cuda_bf16.h>
#include <math.h>
#include <stdint.h>

#define NPTS 16384
#define CD   512
#define DIN  1024
#define DST  16
#define DBCW 64
#define MLPD 1024
#define NCH  128
#define TCH  128

// ================= scratch =================
__device__ __align__(16) float g_f  [NPTS*CD];
__device__ __align__(16) float g_xz [NPTS*2*DIN];
__device__ __align__(16) float g_xc [NPTS*DIN];
__device__ __align__(16) float g_dbc[NPTS*DBCW];
__device__ __align__(16) float g_dt [NPTS*DIN];
__device__ __align__(16) float g_y  [NPTS*DIN];
__device__ __align__(16) float g_x1 [NPTS*CD];
__device__ __align__(16) float g_An [DIN*DST];
__device__ __align__(16) float g_Hc [NCH*DIN*DST];
__device__ __align__(16) float g_sd [NCH*DIN];
__device__ __align__(16) float g_hi [NCH*DIN*DST];
// bf16x3 activations (A side: [hi|lo|hi])
__device__ __align__(16) __nv_bfloat16 g_u3  [NPTS*3*CD];
__device__ __align__(16) __nv_bfloat16 g_xc3 [NPTS*3*DIN];
__device__ __align__(16) __nv_bfloat16 g_dta3[NPTS*128];
__device__ __align__(16) __nv_bfloat16 g_y3  [NPTS*3*DIN];
__device__ __align__(16) __nv_bfloat16 g_h23 [NPTS*3*CD];
__device__ __align__(16) __nv_bfloat16 g_g3  [NPTS*3*MLPD];
// bf16x3 weights (B side: [hi|hi|lo])
__device__ __align__(16) __nv_bfloat16 g_inpw3[2048*3*CD];
__device__ __align__(16) __nv_bfloat16 g_xpw3 [64*3*DIN];
__device__ __align__(16) __nv_bfloat16 g_dtw3 [1024*128];
__device__ __align__(16) __nv_bfloat16 g_outw3[512*3*DIN];
__device__ __align__(16) __nv_bfloat16 g_fw13 [1024*3*CD];
__device__ __align__(16) __nv_bfloat16 g_fw23 [512*3*MLPD];

// ================= helpers =================
__device__ __forceinline__ uint32_t smem_u32(const void* p) {
    uint32_t a;
    asm("{ .reg .u64 t; cvta.to.shared.u64 t, %1; cvt.u32.u64 %0, t; }" : "=r"(a) : "l"(p));
    return a;
}
__device__ __forceinline__ void cp16(uint32_t dst, const void* src) {
    asm volatile("cp.async.cg.shared.global [%0], [%1], 16;" :: "r"(dst), "l"(src) : "memory");
}
#define CP_COMMIT() asm volatile("cp.async.commit_group;" ::: "memory")
#define CP_WAIT(n)  asm volatile("cp.async.wait_group %0;" :: "n"(n) : "memory")
#define LDSM4(r0, r1, r2, r3, addr) \
    asm volatile("ldmatrix.sync.aligned.m8n8.x4.shared.b16 {%0,%1,%2,%3}, [%4];" \
        : "=r"(r0), "=r"(r1), "=r"(r2), "=r"(r3) : "r"(addr))
#define MMA16816(c, a, b) \
    asm volatile("mma.sync.aligned.m16n8k16.row.col.f32.bf16.bf16.f32 " \
        "{%0,%1,%2,%3}, {%4,%5,%6,%7}, {%8,%9}, {%0,%1,%2,%3};" \
        : "+f"((c)[0]), "+f"((c)[1]), "+f"((c)[2]), "+f"((c)[3]) \
        : "r"((a)[0]), "r"((a)[1]), "r"((a)[2]), "r"((a)[3]), "r"((b)[0]), "r"((b)[1]))

__device__ __forceinline__ uint32_t swz(uint32_t off) { return off ^ ((off >> 3) & 0x70); }
__device__ __forceinline__ void bsplit(float x, unsigned short& h, unsigned short& l) {
    __nv_bfloat16 hb = __float2bfloat16(x);
    __nv_bfloat16 lb = __float2bfloat16(x - __bfloat162float(hb));
    h = __bfloat16_as_ushort(hb);
    l = __bfloat16_as_ushort(lb);
}
__device__ __forceinline__ uint32_t pk2(unsigned short a, unsigned short b) {
    return (uint32_t)a | ((uint32_t)b << 16);
}

// ================= bf16x3 tensor-core GEMM (mma.sync HMMA) =================
// C[16384, Nn] = A'[16384, K3] @ B'[Nn, K3]^T, fp32 register accumulate.
// Tile 128 x BN, BK=64, 8 warps as 4x2 (warp tile 32 x BN/2), cp.async double buffer.
// EPI: 0 store fp32 | 1 bias+softplus | 2 residual | 3 bias+gelu->bf16x3 | 4 bias+res+scatter
template<int BN, int EPI>
__global__ __launch_bounds__(256) void tgemm(
    const __nv_bfloat16* __restrict__ A, const __nv_bfloat16* __restrict__ B, int K3,
    float* __restrict__ C, int ldc,
    const float* __restrict__ bias, const float* __restrict__ res,
    const int* __restrict__ gmap, __nv_bfloat16* __restrict__ C3, int c3N)
{
    constexpr int WN  = BN / 2;
    constexpr int NT8 = WN / 8;
    constexpr int STAGE = (128 + BN) * 128;     // bytes per stage (A + B, 128B rows)

    extern __shared__ char dsm[];
    uint32_t base = (smem_u32(dsm) + 1023) & ~1023u;

    const int tid = threadIdx.x;
    const int wid = tid >> 5, lid = tid & 31;
    const int m0 = blockIdx.y * 128;
    const int n0 = blockIdx.x * BN;
    const int wm = (wid >> 1) * 32;
    const int wn = (wid & 1) * WN;
    const int KB = K3 >> 6;

    float acc[2][NT8][4];
#pragma unroll
    for (int mt = 0; mt < 2; mt++)
#pragma unroll
        for (int nt = 0; nt < NT8; nt++)
#pragma unroll
            for (int j = 0; j < 4; j++) acc[mt][nt][j] = 0.f;

    auto load_stage = [&](int kb, int buf) {
        uint32_t sA = base + buf * STAGE;
        uint32_t sB = sA + 16384;
        const __nv_bfloat16* Ab = A + (size_t)m0 * K3 + kb * 64;
        const __nv_bfloat16* Bb = B + (size_t)n0 * K3 + kb * 64;
#pragma unroll
        for (int i = tid; i < 1024; i += 256) {
            int row = i >> 3, c = i & 7;
            uint32_t off = (row << 7) + (c << 4);
            cp16(sA + swz(off), Ab + (size_t)row * K3 + c * 8);
        }
#pragma unroll
        for (int i = tid; i < BN * 8; i += 256) {
            int row = i >> 3, c = i & 7;
            uint32_t off = (row << 7) + (c << 4);
            cp16(sB + swz(off), Bb + (size_t)row * K3 + c * 8);
        }
        CP_COMMIT();
    };

    const int lr = lid & 7, lg = lid >> 3;
    const int rsel = (lg & 1) * 8 + lr;     // row within 16-row group
    const int ksel = (lg >> 1) * 8;         // k column (bf16) within 16

    load_stage(0, 0);

    for (int kb = 0; kb < KB; kb++) {
        if (kb + 1 < KB) { load_stage(kb + 1, (kb + 1) & 1); CP_WAIT(1); }
        else             { CP_WAIT(0); }
        __syncthreads();

        uint32_t sA = base + (kb & 1) * STAGE;
        uint32_t sB = sA + 16384;
#pragma unroll
        for (int ks = 0; ks < 4; ks++) {
            uint32_t a[2][4];
#pragma unroll
            for (int mt = 0; mt < 2; mt++) {
                uint32_t off = (uint32_t)(wm + mt * 16 + rsel) * 128 + (ks * 16 + ksel) * 2;
                LDSM4(a[mt][0], a[mt][1], a[mt][2], a[mt][3], sA + swz(off));
            }
            uint32_t b[NT8][2];
#pragma unroll
            for (int nt2 = 0; nt2 < NT8 / 2; nt2++) {
                uint32_t off = (uint32_t)(wn + nt2 * 16 + rsel) * 128 + (ks * 16 + ksel) * 2;
                uint32_t r0, r1, r2, r3;
                LDSM4(r0, r1, r2, r3, sB + swz(off));
                b[2*nt2][0] = r0; b[2*nt2][1] = r2;
                b[2*nt2+1][0] = r1; b[2*nt2+1][1] = r3;
            }
#pragma unroll
            for (int mt = 0; mt < 2; mt++)
#pragma unroll
                for (int nt = 0; nt < NT8; nt++)
                    MMA16816(acc[mt][nt], a[mt], b[nt]);
        }
        __syncthreads();
    }

    // ---------------- epilogue (register fragments) ----------------
    const int tg = lid >> 2, tq = lid & 3;
#pragma unroll
    for (int mt = 0; mt < 2; mt++) {
#pragma unroll
        for (int half = 0; half < 2; half++) {
            const int m = m0 + wm + mt * 16 + half * 8 + tg;
            const int orow = (EPI == 4) ? gmap[m] : m;
#pragma unroll
            for (int nt = 0; nt < NT8; nt++) {
                const int n = n0 + wn + nt * 8 + tq * 2;
                float v0 = acc[mt][nt][half * 2 + 0];
                float v1 = acc[mt][nt][half * 2 + 1];
                if (EPI == 1 || EPI == 3 || EPI == 4) {
                    float2 bb = *(const float2*)(bias + n);
                    v0 += bb.x; v1 += bb.y;
                }
                if (EPI == 2 || EPI == 4) {
                    float2 rr = *(const float2*)(res + (size_t)m * ldc + n);
                    v0 += rr.x; v1 += rr.y;
                }
                if (EPI == 1) {
                    v0 = (v0 > 0.f) ? (v0 + log1pf(__expf(-v0))) : log1pf(__expf(v0));
                    v1 = (v1 > 0.f) ? (v1 + log1pf(__expf(-v1))) : log1pf(__expf(v1));
                }
                if (EPI == 3) {
                    v0 = 0.5f * v0 * (1.f + erff(v0 * 0.70710678118654752f));
                    v1 = 0.5f * v1 * (1.f + erff(v1 * 0.70710678118654752f));
                    unsigned short h0, l0, h1, l1;
                    bsplit(v0, h0, l0); bsplit(v1, h1, l1);
                    __nv_bfloat16* row3 = C3 + (size_t)m * (3 * c3N);
                    *(uint32_t*)(row3 + n)           = pk2(h0, h1);
                    *(uint32_t*)(row3 + c3N + n)     = pk2(l0, l1);
                    *(uint32_t*)(row3 + 2 * c3N + n) = pk2(h0, h1);
                } else {
                    *(float2*)(C + (size_t)orow * ldc + n) = make_float2(v0, v1);
                }
            }
        }
    }
}

// ================= weight -> bf16x3 (B side: [hi|hi|lo]) =================
__global__ void wconv_kernel(const float* __restrict__ W, __nv_bfloat16* __restrict__ W3,
                             int Nn, int K, int OW, int trans)
{
    int idx = blockIdx.x * blockDim.x + threadIdx.x;
    int n = idx / OW, c = idx % OW;
    if (n >= Nn) return;
    unsigned short out = 0;
    if (c < 3 * K) {
        int seg = c / K, k = c - seg * K;
        float v = trans ? W[(size_t)k * Nn + n] : W[(size_t)n * K + k];
        unsigned short h, l;
        bsplit(v, h, l);
        out = (seg < 2) ? h : l;
    }
    W3[(size_t)n * OW + c] = __ushort_as_bfloat16(out);
}

// dbc[:, 0:32] -> A-side bf16x3 (16384 x 128): [hi|lo|hi|0]
__global__ void dta3_kernel()
{
    int idx = blockIdx.x * blockDim.x + threadIdx.x;
    int t = idx >> 7, c = idx & 127;
    unsigned short out = 0;
    if (c < 96) {
        int seg = c >> 5, k = c & 31;
        float v = g_dbc[(size_t)t * DBCW + k];
        unsigned short h, l;
        bsplit(v, h, l);
        out = (seg == 1) ? l : h;
    }
    g_dta3[idx] = __ushort_as_bfloat16(out);
}

// ================= LayerNorm (+gather/copy) -> bf16x3 [hi|lo|hi] =================
__global__ __launch_bounds__(128) void ln_kernel(
    const float* __restrict__ in, const int* __restrict__ gidx,
    const float* __restrict__ w, const float* __restrict__ b,
    float* __restrict__ copy_out, __nv_bfloat16* __restrict__ out3)
{
    int row = blockIdx.x;
    int src = gidx ? gidx[row] : row;
    float4 v = *((const float4*)(in + (size_t)src * CD) + threadIdx.x);
    if (copy_out)
        *((float4*)(copy_out + (size_t)row * CD) + threadIdx.x) = v;
    float s  = v.x + v.y + v.z + v.w;
    float ss = v.x*v.x + v.y*v.y + v.z*v.z + v.w*v.w;
#pragma unroll
    for (int o = 16; o; o >>= 1) {
        s  += __shfl_xor_sync(0xffffffffu, s,  o);
        ss += __shfl_xor_sync(0xffffffffu, ss, o);
    }
    __shared__ float sh[10];
    if ((threadIdx.x & 31) == 0) {
        sh[threadIdx.x >> 5] = s;
        sh[4 + (threadIdx.x >> 5)] = ss;
    }
    __syncthreads();
    if (threadIdx.x == 0) {
        float S  = sh[0] + sh[1] + sh[2] + sh[3];
        float SS = sh[4] + sh[5] + sh[6] + sh[7];
        float mu = S * (1.f / CD);
        float var = SS * (1.f / CD) - mu * mu;
        sh[8] = mu;
        sh[9] = rsqrtf(var + 1e-5f);
    }
    __syncthreads();
    float mu = sh[8], r = sh[9];
    float4 wv = *((const float4*)w + threadIdx.x);
    float4 bv = *((const float4*)b + threadIdx.x);
    float o[4];
    o[0] = (v.x - mu) * r * wv.x + bv.x;
    o[1] = (v.y - mu) * r * wv.y + bv.y;
    o[2] = (v.z - mu) * r * wv.z + bv.z;
    o[3] = (v.w - mu) * r * wv.w + bv.w;
    unsigned short h[4], l[4];
#pragma unroll
    for (int j = 0; j < 4; j++) bsplit(o[j], h[j], l[j]);
    uint2 wh = make_uint2(pk2(h[0], h[1]), pk2(h[2], h[3]));
    uint2 wl = make_uint2(pk2(l[0], l[1]), pk2(l[2], l[3]));
    __nv_bfloat16* row3 = out3 + (size_t)row * (3 * CD) + 4 * threadIdx.x;
    *(uint2*)(row3)          = wh;
    *(uint2*)(row3 + CD)     = wl;
    *(uint2*)(row3 + 2 * CD) = wh;
}

// ================= conv1d (k=4) + SiLU -> xc fp32 + bf16x3 =================
__global__ void conv_silu_kernel(const float* __restrict__ cw, const float* __restrict__ cb)
{
    int idx = blockIdx.x * blockDim.x + threadIdx.x;
    int t = idx >> 10, d = idx & 1023;
    float acc = cb[d];
#pragma unroll
    for (int k = 0; k < 4; k++) {
        int tt = t - 3 + k;
        if (tt >= 0) acc = fmaf(g_xz[(size_t)tt * (2*DIN) + d], cw[d * 4 + k], acc);
    }
    float sg = 1.f / (1.f + __expf(-acc));
    float xc = acc * sg;
    g_xc[idx] = xc;
    unsigned short h, l;
    bsplit(xc, h, l);
    __nv_bfloat16* row3 = g_xc3 + (size_t)t * (3*DIN) + d;
    row3[0]     = __ushort_as_bfloat16(h);
    row3[DIN]   = __ushort_as_bfloat16(l);
    row3[2*DIN] = __ushort_as_bfloat16(h);
}

__global__ void aneg_kernel(const float* __restrict__ alog)
{
    int i = blockIdx.x * blockDim.x + threadIdx.x;
    g_An[i] = -__expf(alog[i]);
}

// ================= chunked selective scan =================
__global__ __launch_bounds__(128) void scan_local_kernel()
{
    int d = blockIdx.x * 128 + threadIdx.x;
    int c = blockIdx.y;
    int t0 = c * TCH;
    __shared__ float Bsh[TCH][DST];
    __shared__ float Csh[TCH][DST];
    for (int i = threadIdx.x; i < TCH * DST; i += 128) {
        int t = i >> 4, s = i & 15;
        Bsh[t][s] = g_dbc[(size_t)(t0 + t) * DBCW + 32 + s];
        Csh[t][s] = g_dbc[(size_t)(t0 + t) * DBCW + 48 + s];
    }
    __syncthreads();
    float Av[DST], h[DST];
#pragma unroll
    for (int s = 0; s < DST; s++) { Av[s] = g_An[d * DST + s]; h[s] = 0.f; }
    float dts = 0.f;
    for (int t = 0; t < TCH; t++) {
        float dtv = g_dt[(size_t)(t0 + t) * DIN + d];
        float xv  = g_xc[(size_t)(t0 + t) * DIN + d];
        float dtx = dtv * xv;
        dts += dtv;
        float y = 0.f;
#pragma unroll
        for (int s = 0; s < DST; s++) {
            float a = __expf(dtv * Av[s]);
            h[s] = fmaf(a, h[s], dtx * Bsh[t][s]);
            y = fmaf(h[s], Csh[t][s], y);
        }
        g_y[(size_t)(t0 + t) * DIN + d] = y;
    }
#pragma unroll
    for (int s = 0; s < DST; s++)
        g_Hc[((size_t)c * DIN + d) * DST + s] = h[s];
    g_sd[(size_t)c * DIN + d] = dts;
}

__global__ void scan_combine_kernel()
{
    int idx = blockIdx.x * blockDim.x + threadIdx.x;
    int d = idx >> 4;
    float Av = g_An[idx];
    float h = 0.f;
    g_hi[idx] = 0.f;
    for (int c = 1; c < NCH; c++) {
        h = fmaf(__expf(Av * g_sd[(size_t)(c - 1) * DIN + d]), h,
                 g_Hc[(size_t)(c - 1) * DIN * DST + idx]);
        g_hi[(size_t)c * DIN * DST + idx] = h;
    }
}

__global__ __launch_bounds__(128) void scan_correct_kernel(const float* __restrict__ Dskip)
{
    int d = blockIdx.x * 128 + threadIdx.x;
    int c = blockIdx.y;
    int t0 = c * TCH;
    __shared__ float Csh[TCH][DST];
    for (int i = threadIdx.x; i < TCH * DST; i += 128) {
        int t = i >> 4, s = i & 15;
        Csh[t][s] = g_dbc[(size_t)(t0 + t) * DBCW + 48 + s];
    }
    __syncthreads();
    float Av[DST], hi[DST];
#pragma unroll
    for (int s = 0; s < DST; s++) {
        Av[s] = g_An[d * DST + s];
        hi[s] = g_hi[(size_t)c * DIN * DST + d * DST + s];
    }
    float Dv = Dskip[d];
    float cum = 0.f;
    for (int t = 0; t < TCH; t++) {
        float dtv = g_dt[(size_t)(t0 + t) * DIN + d];
        cum += dtv;
        float corr = 0.f;
#pragma unroll
        for (int s = 0; s < DST; s++)
            corr = fmaf(__expf(Av[s] * cum) * hi[s], Csh[t][s], corr);
        float ysum = g_y[(size_t)(t0 + t) * DIN + d] + corr;
        float xv = g_xc[(size_t)(t0 + t) * DIN + d];
        float zv = g_xz[(size_t)(t0 + t) * (2*DIN) + DIN + d];
        float sg = zv / (1.f + __expf(-zv));
        float val = (ysum + xv * Dv) * sg;
        unsigned short h, l;
        bsplit(val, h, l);
        __nv_bfloat16* row3 = g_y3 + (size_t)(t0 + t) * (3*DIN) + d;
        row3[0]     = __ushort_as_bfloat16(h);
        row3[DIN]   = __ushort_as_bfloat16(l);
        row3[2*DIN] = __ushort_as_bfloat16(h);
    }
}

// ================= launch =================
extern "C" void kernel_launch(void* const* d_in, const int* in_sizes, int n_in,
                              void* d_out, int out_size)
{
    (void)in_sizes; (void)n_in; (void)out_size;
    const float* feat  = (const float*)d_in[0];
    const int*   order = (const int*)  d_in[1];
    const float* ln1w  = (const float*)d_in[3];
    const float* ln1b  = (const float*)d_in[4];
    const float* inpw  = (const float*)d_in[5];
    const float* convw = (const float*)d_in[6];
    const float* convb = (const float*)d_in[7];
    const float* xpw   = (const float*)d_in[8];
    const float* dtw   = (const float*)d_in[9];
    const float* dtb   = (const float*)d_in[10];
    const float* alog  = (const float*)d_in[11];
    const float* dskip = (const float*)d_in[12];
    const float* outw  = (const float*)d_in[13];
    const float* ln2w  = (const float*)d_in[14];
    const float* ln2b  = (const float*)d_in[15];
    const float* fw1   = (const float*)d_in[16];
    const float* fb1   = (const float*)d_in[17];
    const float* fw2   = (const float*)d_in[18];
    const float* fb2   = (const float*)d_in[19];
    float* out = (float*)d_out;

    const int SM128 = 2 * (128 + 128) * 128 + 1024;  // 66560
    const int SM64  = 2 * (128 + 64)  * 128 + 1024;  // 50176
    cudaFuncSetAttribute(tgemm<128,0>, cudaFuncAttributeMaxDynamicSharedMemorySize, SM128);
    cudaFuncSetAttribute(tgemm<64,0>,  cudaFuncAttributeMaxDynamicSharedMemorySize, SM64);
    cudaFuncSetAttribute(tgemm<128,1>, cudaFuncAttributeMaxDynamicSharedMemorySize, SM128);
    cudaFuncSetAttribute(tgemm<128,2>, cudaFuncAttributeMaxDynamicSharedMemorySize, SM128);
    cudaFuncSetAttribute(tgemm<128,3>, cudaFuncAttributeMaxDynamicSharedMemorySize, SM128);
    cudaFuncSetAttribute(tgemm<128,4>, cudaFuncAttributeMaxDynamicSharedMemorySize, SM128);

    void *pf, *pxz, *pdbc, *pdt, *px1;
    void *pu3, *pxc3, *pdta3, *py3, *ph23, *pg3;
    void *pw0, *pw1, *pw2, *pw3, *pw4, *pw5;
    cudaGetSymbolAddress(&pf,   g_f);
    cudaGetSymbolAddress(&pxz,  g_xz);
    cudaGetSymbolAddress(&pdbc, g_dbc);
    cudaGetSymbolAddress(&pdt,  g_dt);
    cudaGetSymbolAddress(&px1,  g_x1);
    cudaGetSymbolAddress(&pu3,  g_u3);
    cudaGetSymbolAddress(&pxc3, g_xc3);
    cudaGetSymbolAddress(&pdta3,g_dta3);
    cudaGetSymbolAddress(&py3,  g_y3);
    cudaGetSymbolAddress(&ph23, g_h23);
    cudaGetSymbolAddress(&pg3,  g_g3);
    cudaGetSymbolAddress(&pw0,  g_inpw3);
    cudaGetSymbolAddress(&pw1,  g_xpw3);
    cudaGetSymbolAddress(&pw2,  g_dtw3);
    cudaGetSymbolAddress(&pw3,  g_outw3);
    cudaGetSymbolAddress(&pw4,  g_fw13);
    cudaGetSymbolAddress(&pw5,  g_fw23);

    // weight conversions
    wconv_kernel<<<2048*1536/256, 256>>>(inpw, (__nv_bfloat16*)pw0, 2048, 512, 1536, 0);
    wconv_kernel<<<64*3072/256,   256>>>(xpw,  (__nv_bfloat16*)pw1, 64,   1024, 3072, 0);
    wconv_kernel<<<1024*128/256,  256>>>(dtw,  (__nv_bfloat16*)pw2, 1024, 32,   128,  0);
    wconv_kernel<<<512*3072/256,  256>>>(outw, (__nv_bfloat16*)pw3, 512,  1024, 3072, 0);
    wconv_kernel<<<1024*1536/256, 256>>>(fw1,  (__nv_bfloat16*)pw4, 1024, 512,  1536, 1);
    wconv_kernel<<<512*3072/256,  256>>>(fw2,  (__nv_bfloat16*)pw5, 512,  1024, 3072, 1);
    aneg_kernel<<<(DIN*DST)/256, 256>>>(alog);

    // 1) gather + LN1 -> g_f (raw), u3 (bf16x3)
    ln_kernel<<<NPTS, 128>>>(feat, order, ln1w, ln1b, (float*)pf, (__nv_bfloat16*)pu3);

    // 2) xz = u @ in_proj^T  (16384 x 2048, K3=1536)
    tgemm<128,0><<<dim3(16,128), 256, SM128>>>((__nv_bfloat16*)pu3, (__nv_bfloat16*)pw0, 1536,
                                               (float*)pxz, 2*DIN, nullptr, nullptr, nullptr, nullptr, 0);
    // 3) conv + SiLU -> xc (fp32 + bf16x3)
    conv_silu_kernel<<<(NPTS*DIN)/256, 256>>>(convw, convb);

    // 4) dbc = xc @ x_proj^T  (16384 x 64, K3=3072)
    tgemm<64,0><<<dim3(1,128), 256, SM64>>>((__nv_bfloat16*)pxc3, (__nv_bfloat16*)pw1, 3072,
                                            (float*)pdbc, DBCW, nullptr, nullptr, nullptr, nullptr, 0);

    // 5) dt = softplus(dbc[:, :32] @ dt_proj^T + b)  (16384 x 1024, K3=128)
    dta3_kernel<<<(NPTS*128)/256, 256>>>();
    tgemm<128,1><<<dim3(8,128), 256, SM128>>>((__nv_bfloat16*)pdta3, (__nv_bfloat16*)pw2, 128,
                                              (float*)pdt, DIN, dtb, nullptr, nullptr, nullptr, 0);

    // 6) chunked selective scan + fused gate -> y3
    scan_local_kernel<<<dim3(DIN/128, NCH), 128>>>();
    scan_combine_kernel<<<(DIN*DST)/256, 256>>>();
    scan_correct_kernel<<<dim3(DIN/128, NCH), 128>>>(dskip);

    // 7) x1 = f + y @ out_proj^T  (16384 x 512, K3=3072, fused residual)
    tgemm<128,2><<<dim3(4,128), 256, SM128>>>((__nv_bfloat16*)py3, (__nv_bfloat16*)pw3, 3072,
                                              (float*)px1, CD, nullptr, (const float*)pf, nullptr, nullptr, 0);

    // 8) h2 = LN2(x1) -> bf16x3
    ln_kernel<<<NPTS, 128>>>((const float*)px1, nullptr, ln2w, ln2b, nullptr, (__nv_bfloat16*)ph23);

    // 9) g = gelu(h2 @ ffn_w1 + b1) -> bf16x3  (16384 x 1024, K3=1536)
    tgemm<128,3><<<dim3(8,128), 256, SM128>>>((__nv_bfloat16*)ph23, (__nv_bfloat16*)pw4, 1536,
                                              nullptr, MLPD, fb1, nullptr, nullptr, (__nv_bfloat16*)pg3, MLPD);

    // 10) out[order[m]] = x1[m] + g @ ffn_w2 + b2  (fused residual + scatter)
    tgemm<128,4><<<dim3(4,128), 256, SM128>>>((__nv_bfloat16*)pg3, (__nv_bfloat16*)pw5, 3072,
                                              out, CD, fb2, (const float*)px1, order, nullptr, 0);
}